// round 1
// baseline (speedup 1.0000x reference)
#include <cuda_runtime.h>
#include <cuda_bf16.h>
#include <cstdint>

#define NN   100000
#define NE   600000
#define DD   128
#define NG   200
#define NLAY 5
#define NOUT 10
#define NBLK 98                 // ceil(NN/1024)
#define BETAF 0.0077821404f     // ln(1 + 1/128)
#define OMBF  0.9922178596f     // 1 - BETA

// ---------------- scratch (device globals; no allocations) ----------------
__device__ __align__(16) float d_h  [NN*DD];
__device__ __align__(16) float d_hs [NN*DD];   // h * norm_out (gather source)
__device__ __align__(16) float d_rst[NN*DD];
__device__ float d_norm_out[NN];
__device__ float d_norm_in [NN];
__device__ int   d_deg_out[NN];
__device__ int   d_deg_in [NN];
__device__ int   d_rowptr[NN+1];
__device__ int   d_cursor[NN];
__device__ int   d_col[NE];
__device__ float d_pooled[(NLAY+1)*NG*DD];
__device__ float d_bnsum[2*DD];
__device__ float d_mu[DD];
__device__ float d_istd[DD];
__device__ int   d_bsums[128];

// ---------------- setup kernels ----------------
__global__ void zero_kernel() {
    int i = blockIdx.x * blockDim.x + threadIdx.x;
    if (i < NN) { d_deg_out[i] = 0; d_deg_in[i] = 0; }
    if (i < (NLAY+1)*NG*DD) d_pooled[i] = 0.f;
    if (i < 2*DD) d_bnsum[i] = 0.f;
}

__global__ void deg_kernel(const int* __restrict__ src, const int* __restrict__ dst) {
    int i = blockIdx.x * blockDim.x + threadIdx.x;
    if (i < NE) {
        atomicAdd(&d_deg_out[src[i]], 1);
        atomicAdd(&d_deg_in [dst[i]], 1);
    }
}

__global__ void norm_kernel() {
    int i = blockIdx.x * blockDim.x + threadIdx.x;
    if (i < NN) {
        d_norm_out[i] = rsqrtf((float)max(d_deg_out[i], 1));
        d_norm_in [i] = rsqrtf((float)max(d_deg_in [i], 1));
    }
}

// counting-sort CSR build: scan of deg_in
__global__ void scan_a() {
    __shared__ int sh[256];
    int t = threadIdx.x, base = blockIdx.x * 1024;
    int s = 0;
    #pragma unroll
    for (int i = 0; i < 4; i++) {
        int idx = base + t * 4 + i;
        if (idx < NN) s += d_deg_in[idx];
    }
    sh[t] = s; __syncthreads();
    for (int off = 128; off > 0; off >>= 1) {
        if (t < off) sh[t] += sh[t + off];
        __syncthreads();
    }
    if (t == 0) d_bsums[blockIdx.x] = sh[0];
}

__global__ void scan_b() {
    if (threadIdx.x == 0) {
        int run = 0;
        for (int b = 0; b < NBLK; b++) { int v = d_bsums[b]; d_bsums[b] = run; run += v; }
        d_rowptr[NN] = run;
    }
}

__global__ void scan_c() {
    __shared__ int sh[256];
    int t = threadIdx.x, base = blockIdx.x * 1024;
    int loc[4]; int s = 0;
    #pragma unroll
    for (int i = 0; i < 4; i++) {
        int idx = base + t * 4 + i;
        int v = (idx < NN) ? d_deg_in[idx] : 0;
        loc[i] = s; s += v;
    }
    sh[t] = s; __syncthreads();
    for (int off = 1; off < 256; off <<= 1) {
        int v = (t >= off) ? sh[t - off] : 0;
        __syncthreads();
        sh[t] += v;
        __syncthreads();
    }
    int tpre = (t == 0) ? 0 : sh[t - 1];
    int bpre = d_bsums[blockIdx.x];
    #pragma unroll
    for (int i = 0; i < 4; i++) {
        int idx = base + t * 4 + i;
        if (idx < NN) { int p = bpre + tpre + loc[i]; d_rowptr[idx] = p; d_cursor[idx] = p; }
    }
}

__global__ void fill_kernel(const int* __restrict__ src, const int* __restrict__ dst) {
    int i = blockIdx.x * blockDim.x + threadIdx.x;
    if (i < NE) {
        int d = dst[i];
        int pos = atomicAdd(&d_cursor[d], 1);
        d_col[pos] = src[i];
    }
}

// ---------------- SpMM: warp per dst node, pull from hs ----------------
__global__ __launch_bounds__(256) void spmm_kernel(const float* __restrict__ feat0) {
    int warp = (blockIdx.x * blockDim.x + threadIdx.x) >> 5;
    int lane = threadIdx.x & 31;
    if (warp >= NN) return;
    const float* hprev = feat0 ? feat0 : d_h;
    int beg = d_rowptr[warp], end = d_rowptr[warp + 1];
    float4 acc = make_float4(0.f, 0.f, 0.f, 0.f);
    const float4* hs4 = reinterpret_cast<const float4*>(d_hs);
    for (int e = beg; e < end; e++) {
        int s = __ldg(&d_col[e]);
        float4 v = hs4[s * 32 + lane];
        acc.x += v.x; acc.y += v.y; acc.z += v.z; acc.w += v.w;
    }
    float ni = 0.9f * d_norm_in[warp];
    float4 hv = reinterpret_cast<const float4*>(hprev)[warp * 32 + lane];
    float4 r;
    r.x = ni * acc.x + 0.1f * hv.x;
    r.y = ni * acc.y + 0.1f * hv.y;
    r.z = ni * acc.z + 0.1f * hv.z;
    r.w = ni * acc.w + 0.1f * hv.w;
    reinterpret_cast<float4*>(d_rst)[warp * 32 + lane] = r;
}

// ---------------- GEMM: rst = (1-B)*rst + B*(rst@W) + bias, in place ----
// bf16 mma.sync (fp32 accumulate); bf16 error enters only through the
// BETA-scaled (~0.0078x) term, so it is numerically negligible.
__global__ __launch_bounds__(256) void gemm_kernel(const float* __restrict__ W,
                                                   const float* __restrict__ bias) {
    __shared__ __nv_bfloat16 As[128][72];   // 64 k-cols + 8 pad
    __shared__ __nv_bfloat16 Ws[64][136];   // 128 n-cols + 8 pad
    int t = threadIdx.x, lane = t & 31, wid = t >> 5;
    int rowbase = blockIdx.x * 128;
    float acc[16][4];
    #pragma unroll
    for (int i = 0; i < 16; i++) { acc[i][0]=0.f; acc[i][1]=0.f; acc[i][2]=0.f; acc[i][3]=0.f; }

    for (int kk = 0; kk < 128; kk += 64) {
        // stage A tile (128 rows x 64 k) fp32 -> bf16
        for (int i = t; i < 128 * 16; i += 256) {
            int r = i >> 4, c4 = i & 15;
            int grow = rowbase + r;
            float4 v = make_float4(0.f, 0.f, 0.f, 0.f);
            if (grow < NN)
                v = reinterpret_cast<const float4*>(d_rst)[grow * 32 + (kk >> 2) + c4];
            __nv_bfloat162* ap = reinterpret_cast<__nv_bfloat162*>(&As[r][c4 * 4]);
            ap[0] = __floats2bfloat162_rn(v.x, v.y);
            ap[1] = __floats2bfloat162_rn(v.z, v.w);
        }
        // stage W tile (64 k x 128 n) fp32 -> bf16
        for (int i = t; i < 64 * 32; i += 256) {
            int r = i >> 5, c4 = i & 31;
            float4 v = reinterpret_cast<const float4*>(W)[(kk + r) * 32 + c4];
            __nv_bfloat162* wp = reinterpret_cast<__nv_bfloat162*>(&Ws[r][c4 * 4]);
            wp[0] = __floats2bfloat162_rn(v.x, v.y);
            wp[1] = __floats2bfloat162_rn(v.z, v.w);
        }
        __syncthreads();

        #pragma unroll
        for (int k0 = 0; k0 < 64; k0 += 16) {
            uint32_t a[4];
            unsigned aaddr = (unsigned)__cvta_generic_to_shared(
                &As[wid * 16 + (lane & 15)][k0 + ((lane >> 1) & 8)]);
            asm volatile("ldmatrix.sync.aligned.m8n8.x4.shared.b16 {%0,%1,%2,%3}, [%4];"
                         : "=r"(a[0]), "=r"(a[1]), "=r"(a[2]), "=r"(a[3]) : "r"(aaddr));
            unsigned bbase = (unsigned)__cvta_generic_to_shared(&Ws[k0 + (lane & 15)][0]);
            #pragma unroll
            for (int nb = 0; nb < 16; nb++) {
                uint32_t b[2];
                asm volatile("ldmatrix.sync.aligned.m8n8.x2.trans.shared.b16 {%0,%1}, [%2];"
                             : "=r"(b[0]), "=r"(b[1]) : "r"(bbase + nb * 16));
                asm volatile("mma.sync.aligned.m16n8k16.row.col.f32.bf16.bf16.f32 "
                             "{%0,%1,%2,%3},{%4,%5,%6,%7},{%8,%9},{%0,%1,%2,%3};"
                             : "+f"(acc[nb][0]), "+f"(acc[nb][1]), "+f"(acc[nb][2]), "+f"(acc[nb][3])
                             : "r"(a[0]), "r"(a[1]), "r"(a[2]), "r"(a[3]), "r"(b[0]), "r"(b[1]));
            }
        }
        __syncthreads();
    }
    // epilogue: in-place (residual path in fp32)
    int r0 = rowbase + wid * 16 + (lane >> 2);
    int r1 = r0 + 8;
    #pragma unroll
    for (int nb = 0; nb < 16; nb++) {
        int c = nb * 8 + (lane & 3) * 2;
        float b0 = bias[c], b1 = bias[c + 1];
        if (r0 < NN) {
            float* p = &d_rst[r0 * 128 + c];
            p[0] = OMBF * p[0] + BETAF * acc[nb][0] + b0;
            p[1] = OMBF * p[1] + BETAF * acc[nb][1] + b1;
        }
        if (r1 < NN) {
            float* p = &d_rst[r1 * 128 + c];
            p[0] = OMBF * p[0] + BETAF * acc[nb][2] + b0;
            p[1] = OMBF * p[1] + BETAF * acc[nb][3] + b1;
        }
    }
}

// ---------------- BN statistics ----------------
__global__ __launch_bounds__(256) void bnstats_kernel() {
    __shared__ float ss[256], sq[256];
    int t = threadIdx.x;
    float s = 0.f, q = 0.f;
    int stride = gridDim.x * 256;   // multiple of 128 -> dim fixed per thread
    for (int i = blockIdx.x * 256 + t; i < NN * DD; i += stride) {
        float v = d_rst[i];
        s += v; q += v * v;
    }
    ss[t] = s; sq[t] = q; __syncthreads();
    if (t < 128) {
        atomicAdd(&d_bnsum[t],        ss[t] + ss[t + 128]);
        atomicAdd(&d_bnsum[128 + t],  sq[t] + sq[t + 128]);
    }
}

__global__ void finalize_kernel() {
    int t = threadIdx.x;   // 128 threads
    float s = d_bnsum[t], q = d_bnsum[128 + t];
    float mu = s * (1.0f / NN);
    float var = q * (1.0f / NN) - mu * mu;
    d_mu[t] = mu;
    d_istd[t] = rsqrtf(var + 1e-5f);
    d_bnsum[t] = 0.f; d_bnsum[128 + t] = 0.f;  // ready for next layer / next launch
}

// ---------------- BN+ReLU (+ hs prescale + per-graph pooling) ----------------
template <bool INIT>
__global__ __launch_bounds__(256) void epilogue_kernel(const float* __restrict__ src,
                                                       const int* __restrict__ gid,
                                                       int pslot,
                                                       const float* __restrict__ bng,
                                                       const float* __restrict__ bnb) {
    __shared__ float spool[16][128];
    int t = threadIdx.x;
    int base = blockIdx.x * 256;
    int nodes = min(256, NN - base);
    if (nodes <= 0) return;
    int g0 = gid[base];
    int span = gid[base + nodes - 1] - g0 + 1;
    bool fits = (span <= 16);
    if (fits) for (int i = t; i < span * 128; i += 256) ((float*)spool)[i] = 0.f;
    __syncthreads();

    int d = t & 127;
    int half = t >> 7;
    float bg = 0.f, bb = 0.f, mu = 0.f, is = 0.f;
    if (!INIT) { bg = bng[d]; bb = bnb[d]; mu = d_mu[d]; is = d_istd[d]; }
    const float* sp = INIT ? src : d_rst;

    float racc = 0.f; int rlg = -1;
    for (int i = half; i < nodes; i += 2) {
        int n = base + i;
        float v = sp[n * 128 + d];
        float y;
        if (INIT) y = v;
        else {
            y = fmaxf((v - mu) * is * bg + bb, 0.0f);
            d_h[n * 128 + d] = y;
        }
        d_hs[n * 128 + d] = y * d_norm_out[n];
        int lg = gid[n] - g0;
        if (fits) {
            if (lg != rlg) {
                if (rlg >= 0) atomicAdd(&spool[rlg][d], racc);
                rlg = lg; racc = 0.f;
            }
            racc += y;
        } else {
            atomicAdd(&d_pooled[(pslot * NG + g0 + lg) * 128 + d], y);
        }
    }
    if (fits && rlg >= 0) atomicAdd(&spool[rlg][d], racc);
    __syncthreads();
    if (fits)
        for (int lg = half; lg < span; lg += 2)
            atomicAdd(&d_pooled[(pslot * NG + g0 + lg) * 128 + d], spool[lg][d]);
}

// ---------------- readout: scores + log_softmax + mean_pooled ----------------
__global__ void final_kernel(const float* __restrict__ lin_w,
                             const float* __restrict__ lin_b,
                             float* __restrict__ out) {
    __shared__ float sp[6][128];
    __shared__ float sc[NOUT];
    int g = blockIdx.x, t = threadIdx.x;   // 128 threads
    for (int i = t; i < 6 * 128; i += 128)
        sp[i / 128][i & 127] = d_pooled[((i / 128) * NG + g) * 128 + (i & 127)];
    __syncthreads();
    if (t < NOUT) {
        float s = 0.f;
        for (int i = 0; i < 6; i++) {
            s += lin_b[i * NOUT + t];
            const float* w = lin_w + i * 128 * NOUT;
            float ps = 0.f;
            for (int k = 0; k < 128; k++) ps += sp[i][k] * w[k * NOUT + t];
            s += ps;
        }
        sc[t] = s;
    }
    __syncthreads();
    if (t < NOUT) {
        float m = sc[0];
        #pragma unroll
        for (int i = 1; i < NOUT; i++) m = fmaxf(m, sc[i]);
        float lse = 0.f;
        #pragma unroll
        for (int i = 0; i < NOUT; i++) lse += expf(sc[i] - m);
        lse = logf(lse);
        out[g * NOUT + t] = sc[t] - m - lse;
    }
    float mp = sp[1][t] + sp[2][t] + sp[3][t] + sp[4][t] + sp[5][t];
    out[NG * NOUT + g * 128 + t] = mp * 0.2f;
}

// ---------------- host launcher ----------------
extern "C" void kernel_launch(void* const* d_in, const int* in_sizes, int n_in,
                              void* d_out, int out_size) {
    const float* feat  = (const float*)d_in[0];
    const int*   src   = (const int*)  d_in[1];
    const int*   dst   = (const int*)  d_in[2];
    const int*   gid   = (const int*)  d_in[3];
    const float* gcn_w = (const float*)d_in[4];
    const float* gcn_b = (const float*)d_in[5];
    const float* bn_g  = (const float*)d_in[6];
    const float* bn_b  = (const float*)d_in[7];
    const float* lin_w = (const float*)d_in[8];
    const float* lin_b = (const float*)d_in[9];
    float* out = (float*)d_out;
    (void)in_sizes; (void)n_in; (void)out_size;

    zero_kernel<<<600, 256>>>();
    deg_kernel<<<(NE + 255) / 256, 256>>>(src, dst);
    norm_kernel<<<(NN + 255) / 256, 256>>>();
    scan_a<<<NBLK, 256>>>();
    scan_b<<<1, 32>>>();
    scan_c<<<NBLK, 256>>>();
    fill_kernel<<<(NE + 255) / 256, 256>>>(src, dst);
    // hs = feat * norm_out ; pooled[0] = segment_sum(feat)
    epilogue_kernel<true><<<(NN + 255) / 256, 256>>>(feat, gid, 0, nullptr, nullptr);

    for (int l = 0; l < NLAY; l++) {
        spmm_kernel<<<(NN * 32 + 255) / 256, 256>>>(l == 0 ? feat : nullptr);
        gemm_kernel<<<(NN + 127) / 128, 256>>>(gcn_w + l * DD * DD, gcn_b + l * DD);
        bnstats_kernel<<<2048, 256>>>();
        finalize_kernel<<<1, 128>>>();
        epilogue_kernel<false><<<(NN + 255) / 256, 256>>>(nullptr, gid, l + 1,
                                                          bn_g + l * DD, bn_b + l * DD);
    }
    final_kernel<<<NG, 128>>>(lin_w, lin_b, out);
}